// round 14
// baseline (speedup 1.0000x reference)
#include <cuda_runtime.h>
#include <cuda_fp16.h>
#include <cstdint>

#define DEVINL __device__ __forceinline__

namespace {

constexpr int NB = 2, NH = 16, S = 2048, D = 128, HK = 4, NI = 2048;
constexpr float SCALE = 0.08838834764831843f;   // 128^-0.5

constexpr int BM = 128;            // q rows per CTA
constexpr int BI = 64;             // i-chunk
constexpr int NCHUNK = NI / BI;    // 32
constexpr int THREADS = 256;       // 8 warps, each owns 16 q-rows

// smem: two 48KB stages; Q (32KB) staged through stage 1 before chunk1 load
constexpr uint32_t OFF_K = 0;
constexpr uint32_t OFF_U = 16384;
constexpr uint32_t OFF_V = 32768;
constexpr uint32_t STAGE_BYTES = 49152;
constexpr uint32_t SMEM_TOTAL  = 2 * STAGE_BYTES;   // 98304 -> 2 CTAs/SM

} // namespace

// fp16 scratch (static device arrays: allowed scratch form)
__device__ __half g_Kh[(size_t)HK * NI * D];
__device__ __half g_Uh[(size_t)HK * NI * D];
__device__ __half g_Vh[(size_t)HK * NI * D];

// ======================= K/U/V converter =======================

__global__ void conv_kuv(const float* __restrict__ k, const float* __restrict__ u,
                         const float* __restrict__ v) {
    int i = blockIdx.x * 256 + threadIdx.x;
    const float* s;
    __half* dd;
    if (blockIdx.y == 0)      { s = k; dd = g_Kh; }
    else if (blockIdx.y == 1) { s = u; dd = g_Uh; }
    else                      { s = v; dd = g_Vh; }
    float4 val = reinterpret_cast<const float4*>(s)[i];
    __half2* d = reinterpret_cast<__half2*>(dd);
    d[2 * i]     = __floats2half2_rn(val.x, val.y);
    d[2 * i + 1] = __floats2half2_rn(val.z, val.w);
}

// ======================= PTX helpers =======================

DEVINL uint32_t smem_u32(const void* p) {
    uint32_t a;
    asm("{ .reg .u64 t; cvta.to.shared.u64 t, %1; cvt.u32.u64 %0, t; }" : "=r"(a) : "l"(p));
    return a;
}

DEVINL void cp16(uint32_t dst, const void* gsrc) {
    asm volatile("cp.async.cg.shared.global [%0], [%1], 16;"
                 :: "r"(dst), "l"(__cvta_generic_to_global(gsrc)) : "memory");
}
#define CP_COMMIT() asm volatile("cp.async.commit_group;" ::: "memory")
#define CP_WAIT1()  asm volatile("cp.async.wait_group 1;" ::: "memory")

DEVINL void ldsm_x4(uint32_t addr, uint32_t* r) {
    asm volatile("ldmatrix.sync.aligned.m8n8.x4.shared.b16 {%0,%1,%2,%3}, [%4];"
                 : "=r"(r[0]), "=r"(r[1]), "=r"(r[2]), "=r"(r[3]) : "r"(addr));
}
DEVINL void ldsm_x4_t(uint32_t addr, uint32_t* r) {
    asm volatile("ldmatrix.sync.aligned.m8n8.x4.trans.shared.b16 {%0,%1,%2,%3}, [%4];"
                 : "=r"(r[0]), "=r"(r[1]), "=r"(r[2]), "=r"(r[3]) : "r"(addr));
}
DEVINL void mma16816(float* d, const uint32_t* a, uint32_t b0, uint32_t b1) {
    asm volatile("mma.sync.aligned.m16n8k16.row.col.f32.f16.f16.f32 "
                 "{%0,%1,%2,%3},{%4,%5,%6,%7},{%8,%9},{%0,%1,%2,%3};"
                 : "+f"(d[0]), "+f"(d[1]), "+f"(d[2]), "+f"(d[3])
                 : "r"(a[0]), "r"(a[1]), "r"(a[2]), "r"(a[3]), "r"(b0), "r"(b1));
}
DEVINL float tanhapx(float x) {
    float y;
    asm("tanh.approx.f32 %0, %1;" : "=f"(y) : "f"(x));
    return y;
}

// gate pair: inputs already carry SCALE (folded into Q). a = silu(m) * n
DEVINL uint32_t gate2(float m0, float m1, float n0, float n1) {
    float s0 = 0.5f * m0 * (1.0f + tanhapx(0.5f * m0));
    float s1 = 0.5f * m1 * (1.0f + tanhapx(0.5f * m1));
    __half2 h = __floats2half2_rn(s0 * n0, s1 * n1);
    return *reinterpret_cast<uint32_t*>(&h);
}

// ======================= main kernel =======================

__global__ __launch_bounds__(THREADS, 2)
void flash_mlp_mma(const float* __restrict__ gQ, float* __restrict__ gO) {
    extern __shared__ char smem[];
    const uint32_t sb = smem_u32(smem);

    const int tid  = threadIdx.x;
    const int wid  = tid >> 5;          // 0..7 : each warp owns 16 q-rows
    const int lane = tid & 31;

    const int tileM = blockIdx.x;       // 0..15
    const int bh    = blockIdx.y;       // 0..31
    const int hk    = (bh & 15) >> 2;

    const float*  qG = gQ   + ((size_t)bh * S + (size_t)tileM * BM) * D;
    const __half* kG = g_Kh + (size_t)hk * NI * D;
    const __half* uG = g_Uh + (size_t)hk * NI * D;
    const __half* vG = g_Vh + (size_t)hk * NI * D;
    float*        oB = gO   + ((size_t)bh * S + (size_t)tileM * BM) * D;

    auto load_chunk = [&](int c, int stg) {
        uint32_t base = sb + (uint32_t)stg * STAGE_BYTES;
        #pragma unroll
        for (int j = 0; j < 4; ++j) {
            int idx = tid + j * THREADS;    // 0..1023
            int r   = idx >> 4;             // 0..63
            int cc  = idx & 15;
            uint32_t so = r * 256 + ((cc * 16) ^ ((r & 7) << 4));
            const size_t go = (size_t)(c * BI + r) * D + cc * 8;
            cp16(base + OFF_K + so, kG + go);
            cp16(base + OFF_U + so, uG + go);
            cp16(base + OFF_V + so, vG + go);
        }
    };

    // chunk 0 -> stage 0 (async, overlaps Q conversion)
    load_chunk(0, 0); CP_COMMIT();

    // ---- Q: fp32 LDG -> *SCALE -> fp16 -> swizzled (staged in stage-1 buffer) ----
    #pragma unroll 4
    for (int j = 0; j < 16; ++j) {
        int idx = tid + j * THREADS;      // 0..4095
        int r   = idx >> 5;               // row 0..127
        int f4  = idx & 31;               // float4 within row
        float4 v = reinterpret_cast<const float4*>(qG)[(size_t)r * 32 + f4];
        __half2 h0 = __floats2half2_rn(v.x * SCALE, v.y * SCALE);
        __half2 h1 = __floats2half2_rn(v.z * SCALE, v.w * SCALE);
        int cc = f4 >> 1, sub = f4 & 1;
        uint32_t so = STAGE_BYTES + (uint32_t)r * 256 +
                      (((uint32_t)cc * 16) ^ ((r & 7) << 4)) + sub * 8;
        *reinterpret_cast<__half2*>(smem + so)     = h0;
        *reinterpret_cast<__half2*>(smem + so + 4) = h1;
    }
    __syncthreads();

    // ---- hoist Q fragments (16 rows per warp, persistent across chunks) ----
    uint32_t qfr[8][4];
    #pragma unroll
    for (int ks = 0; ks < 8; ++ks) {
        int r = wid * 16 + (lane & 15);
        uint32_t byt = ks * 32 + ((lane >> 4) << 4);
        ldsm_x4(sb + STAGE_BYTES + r * 256 + (byt ^ ((r & 7) << 4)), qfr[ks]);
    }
    __syncthreads();                      // Q fully consumed; stage 1 reusable

    // chunk 1 -> stage 1
    load_chunk(1, 1); CP_COMMIT();

    float accO[16][4];
    #pragma unroll
    for (int b = 0; b < 16; ++b)
        #pragma unroll
        for (int e = 0; e < 4; ++e) accO[b][e] = 0.0f;

    for (int c = 0; c < NCHUNK; ++c) {
        CP_WAIT1();                       // stage for chunk c complete
        __syncthreads();
        const uint32_t stg = sb + (uint32_t)(c & 1) * STAGE_BYTES;

        uint32_t aFr[4][4];               // gated A, four k16 fragments (i=64)

        // ===== GEMM1/2 per 16-wide i-block, gate immediately (short accM/N) =====
        #pragma unroll
        for (int pt = 0; pt < 4; ++pt) {
            float accM[2][4], accN[2][4];
            #pragma unroll
            for (int b = 0; b < 2; ++b)
                #pragma unroll
                for (int e = 0; e < 4; ++e) { accM[b][e] = 0.0f; accN[b][e] = 0.0f; }

            #pragma unroll
            for (int ks = 0; ks < 8; ++ks) {
                uint32_t bk[4], bu[4];
                int g  = lane >> 3;
                int nr = pt * 16 + ((g & 2) << 2) + (lane & 7);
                uint32_t byt = ks * 32 + ((g & 1) << 4);
                uint32_t so  = nr * 256 + (byt ^ ((nr & 7) << 4));
                ldsm_x4(stg + OFF_K + so, bk);
                ldsm_x4(stg + OFF_U + so, bu);
                mma16816(accM[0], qfr[ks], bk[0], bk[1]);
                mma16816(accM[1], qfr[ks], bk[2], bk[3]);
                mma16816(accN[0], qfr[ks], bu[0], bu[1]);
                mma16816(accN[1], qfr[ks], bu[2], bu[3]);
            }

            aFr[pt][0] = gate2(accM[0][0], accM[0][1], accN[0][0], accN[0][1]);
            aFr[pt][1] = gate2(accM[0][2], accM[0][3], accN[0][2], accN[0][3]);
            aFr[pt][2] = gate2(accM[1][0], accM[1][1], accN[1][0], accN[1][1]);
            aFr[pt][3] = gate2(accM[1][2], accM[1][3], accN[1][2], accN[1][3]);
        }

        // ===== GEMM3: O += A V  (16 rows x 128 cols, k = 64 i) =====
        #pragma unroll
        for (int ks2 = 0; ks2 < 4; ++ks2) {
            #pragma unroll
            for (int p = 0; p < 8; ++p) {        // 8 x n16 covers d=128
                uint32_t bv[4];
                int g  = lane >> 3;
                int kr = ks2 * 16 + ((g & 1) << 3) + (lane & 7);
                uint32_t byt = p * 32 + ((g >> 1) << 4);
                ldsm_x4_t(stg + OFF_V + kr * 256 + (byt ^ ((kr & 7) << 4)), bv);
                mma16816(accO[2 * p + 0], aFr[ks2], bv[0], bv[1]);
                mma16816(accO[2 * p + 1], aFr[ks2], bv[2], bv[3]);
            }
        }

        __syncthreads();                  // stage (c&1) fully consumed
        if (c + 2 < NCHUNK) load_chunk(c + 2, c & 1);
        CP_COMMIT();                      // uniform group accounting
    }

    // ================= write O (16 rows x 128 cols per warp) =================
    {
        const int g = lane >> 2, q = lane & 3;
        const int r0 = wid * 16 + g;
        #pragma unroll
        for (int nt = 0; nt < 16; ++nt) {
            int col = nt * 8 + q * 2;
            *reinterpret_cast<float2*>(oB + (size_t)r0 * D + col) =
                make_float2(accO[nt][0], accO[nt][1]);
            *reinterpret_cast<float2*>(oB + (size_t)(r0 + 8) * D + col) =
                make_float2(accO[nt][2], accO[nt][3]);
        }
    }
}

// ======================= launch =======================

extern "C" void kernel_launch(void* const* d_in, const int* in_sizes, int n_in,
                              void* d_out, int out_size) {
    const float* Q = (const float*)d_in[0];
    const float* K = (const float*)d_in[1];
    const float* U = (const float*)d_in[2];
    const float* V = (const float*)d_in[3];
    float* O = (float*)d_out;

    dim3 gk((HK * NI * D / 4) / 256, 3);
    conv_kuv<<<gk, 256>>>(K, U, V);

    cudaFuncSetAttribute(flash_mlp_mma,
                         cudaFuncAttributeMaxDynamicSharedMemorySize, SMEM_TOTAL);
    dim3 grid(S / BM, NB * NH);   // (16, 32)
    flash_mlp_mma<<<grid, THREADS, SMEM_TOTAL>>>(Q, O);
}

// round 15
// speedup vs baseline: 1.3209x; 1.3209x over previous
#include <cuda_runtime.h>
#include <cuda_fp16.h>
#include <cstdint>

#define DEVINL __device__ __forceinline__

namespace {

constexpr int NB = 2, NH = 16, S = 2048, D = 128, HK = 4, NI = 2048;
constexpr float SCALE = 0.08838834764831843f;   // 128^-0.5

constexpr int BM = 64;             // q rows per CTA
constexpr int BI = 64;             // i-chunk
constexpr int NCHUNK = NI / BI;    // 32
constexpr int THREADS = 128;       // 4 warps, each owns 16 q-rows

// smem: two 48KB stages; Q staged through stage 1 before chunk1 load
constexpr uint32_t OFF_K = 0;
constexpr uint32_t OFF_U = 16384;
constexpr uint32_t OFF_V = 32768;
constexpr uint32_t STAGE_BYTES = 49152;
constexpr uint32_t SMEM_TOTAL  = 2 * STAGE_BYTES;   // 98304 (2 CTAs/SM)

} // namespace

// fp16 scratch (static device arrays: allowed scratch form)
__device__ __half g_Kh[(size_t)HK * NI * D];
__device__ __half g_Uh[(size_t)HK * NI * D];
__device__ __half g_Vh[(size_t)HK * NI * D];

// ======================= K/U/V converter =======================

__global__ void conv_kuv(const float* __restrict__ k, const float* __restrict__ u,
                         const float* __restrict__ v) {
    int i = blockIdx.x * 256 + threadIdx.x;
    const float* s;
    __half* dd;
    if (blockIdx.y == 0)      { s = k; dd = g_Kh; }
    else if (blockIdx.y == 1) { s = u; dd = g_Uh; }
    else                      { s = v; dd = g_Vh; }
    float4 val = reinterpret_cast<const float4*>(s)[i];
    __half2* d = reinterpret_cast<__half2*>(dd);
    d[2 * i]     = __floats2half2_rn(val.x, val.y);
    d[2 * i + 1] = __floats2half2_rn(val.z, val.w);
}

// ======================= PTX helpers =======================

DEVINL uint32_t smem_u32(const void* p) {
    uint32_t a;
    asm("{ .reg .u64 t; cvta.to.shared.u64 t, %1; cvt.u32.u64 %0, t; }" : "=r"(a) : "l"(p));
    return a;
}

DEVINL void cp16(uint32_t dst, const void* gsrc) {
    asm volatile("cp.async.cg.shared.global [%0], [%1], 16;"
                 :: "r"(dst), "l"(__cvta_generic_to_global(gsrc)) : "memory");
}
#define CP_COMMIT() asm volatile("cp.async.commit_group;" ::: "memory")
#define CP_WAIT1()  asm volatile("cp.async.wait_group 1;" ::: "memory")

DEVINL void ldsm_x4(uint32_t addr, uint32_t* r) {
    asm volatile("ldmatrix.sync.aligned.m8n8.x4.shared.b16 {%0,%1,%2,%3}, [%4];"
                 : "=r"(r[0]), "=r"(r[1]), "=r"(r[2]), "=r"(r[3]) : "r"(addr));
}
DEVINL void ldsm_x4_t(uint32_t addr, uint32_t* r) {
    asm volatile("ldmatrix.sync.aligned.m8n8.x4.trans.shared.b16 {%0,%1,%2,%3}, [%4];"
                 : "=r"(r[0]), "=r"(r[1]), "=r"(r[2]), "=r"(r[3]) : "r"(addr));
}
DEVINL void mma16816(float* d, const uint32_t* a, uint32_t b0, uint32_t b1) {
    asm volatile("mma.sync.aligned.m16n8k16.row.col.f32.f16.f16.f32 "
                 "{%0,%1,%2,%3},{%4,%5,%6,%7},{%8,%9},{%0,%1,%2,%3};"
                 : "+f"(d[0]), "+f"(d[1]), "+f"(d[2]), "+f"(d[3])
                 : "r"(a[0]), "r"(a[1]), "r"(a[2]), "r"(a[3]), "r"(b0), "r"(b1));
}
DEVINL float tanhapx(float x) {
    float y;
    asm("tanh.approx.f32 %0, %1;" : "=f"(y) : "f"(x));
    return y;
}

// gate pair: inputs already carry SCALE (folded into Q). a = silu(m) * n
DEVINL uint32_t gate2(float m0, float m1, float n0, float n1) {
    float s0 = 0.5f * m0 * (1.0f + tanhapx(0.5f * m0));
    float s1 = 0.5f * m1 * (1.0f + tanhapx(0.5f * m1));
    __half2 h = __floats2half2_rn(s0 * n0, s1 * n1);
    return *reinterpret_cast<uint32_t*>(&h);
}

// ======================= main kernel =======================

__global__ __launch_bounds__(THREADS, 2)
void flash_mlp_mma(const float* __restrict__ gQ, float* __restrict__ gO) {
    extern __shared__ char smem[];
    const uint32_t sb = smem_u32(smem);

    const int tid  = threadIdx.x;
    const int wid  = tid >> 5;          // 0..3 : each warp owns 16 q-rows
    const int lane = tid & 31;

    const int tileM = blockIdx.x;       // 0..31
    const int bh    = blockIdx.y;       // 0..31
    const int hk    = (bh & 15) >> 2;

    const float*  qG = gQ   + ((size_t)bh * S + (size_t)tileM * BM) * D;
    const __half* kG = g_Kh + (size_t)hk * NI * D;
    const __half* uG = g_Uh + (size_t)hk * NI * D;
    const __half* vG = g_Vh + (size_t)hk * NI * D;
    float*        oB = gO   + ((size_t)bh * S + (size_t)tileM * BM) * D;

    auto load_chunk = [&](int c, int stg) {
        uint32_t base = sb + (uint32_t)stg * STAGE_BYTES;
        #pragma unroll
        for (int j = 0; j < 8; ++j) {
            int idx = tid + j * THREADS;    // 0..1023
            int r   = idx >> 4;             // 0..63
            int cc  = idx & 15;
            uint32_t so = r * 256 + ((cc * 16) ^ ((r & 7) << 4));
            const size_t go = (size_t)(c * BI + r) * D + cc * 8;
            cp16(base + OFF_K + so, kG + go);
            cp16(base + OFF_U + so, uG + go);
            cp16(base + OFF_V + so, vG + go);
        }
    };

    // chunk 0 -> stage 0 (async, overlaps Q conversion)
    load_chunk(0, 0); CP_COMMIT();

    // ---- Q: fp32 LDG -> *SCALE -> fp16 -> swizzled (staged in stage-1 buffer) ----
    #pragma unroll 4
    for (int j = 0; j < 16; ++j) {
        int idx = tid + j * THREADS;      // 0..2047
        int r   = idx >> 5;               // row 0..63
        int f4  = idx & 31;               // float4 within row
        float4 v = reinterpret_cast<const float4*>(qG)[(size_t)r * 32 + f4];
        __half2 h0 = __floats2half2_rn(v.x * SCALE, v.y * SCALE);
        __half2 h1 = __floats2half2_rn(v.z * SCALE, v.w * SCALE);
        int cc = f4 >> 1, sub = f4 & 1;
        uint32_t so = STAGE_BYTES + (uint32_t)r * 256 +
                      (((uint32_t)cc * 16) ^ ((r & 7) << 4)) + sub * 8;
        *reinterpret_cast<__half2*>(smem + so)     = h0;
        *reinterpret_cast<__half2*>(smem + so + 4) = h1;
    }
    __syncthreads();

    // ---- hoist Q fragments (16 rows per warp, persistent across chunks) ----
    uint32_t qfr[8][4];
    #pragma unroll
    for (int ks = 0; ks < 8; ++ks) {
        int r = wid * 16 + (lane & 15);
        uint32_t byt = ks * 32 + ((lane >> 4) << 4);
        ldsm_x4(sb + STAGE_BYTES + r * 256 + (byt ^ ((r & 7) << 4)), qfr[ks]);
    }
    __syncthreads();                      // Q fully consumed; stage 1 reusable

    // chunk 1 -> stage 1
    load_chunk(1, 1); CP_COMMIT();

    float accO[16][4];
    #pragma unroll
    for (int b = 0; b < 16; ++b)
        #pragma unroll
        for (int e = 0; e < 4; ++e) accO[b][e] = 0.0f;

    for (int c = 0; c < NCHUNK; ++c) {
        CP_WAIT1();                       // stage for chunk c complete
        __syncthreads();
        const uint32_t stg = sb + (uint32_t)(c & 1) * STAGE_BYTES;

        // ===== fused per-16-i-slice pipeline: GEMM1/2(pt) -> gate -> GEMM3(pt) ====
        #pragma unroll
        for (int pt = 0; pt < 4; ++pt) {
            // --- GEMM1/2: scores for this warp's 16 rows x 16 i ---
            float accM[2][4], accN[2][4];
            #pragma unroll
            for (int b = 0; b < 2; ++b)
                #pragma unroll
                for (int e = 0; e < 4; ++e) { accM[b][e] = 0.0f; accN[b][e] = 0.0f; }

            #pragma unroll
            for (int ks = 0; ks < 8; ++ks) {
                uint32_t bk[4], bu[4];
                int g  = lane >> 3;
                int nr = pt * 16 + ((g & 2) << 2) + (lane & 7);
                uint32_t byt = ks * 32 + ((g & 1) << 4);
                uint32_t so  = nr * 256 + (byt ^ ((nr & 7) << 4));
                ldsm_x4(stg + OFF_K + so, bk);
                ldsm_x4(stg + OFF_U + so, bu);
                mma16816(accM[0], qfr[ks], bk[0], bk[1]);
                mma16816(accM[1], qfr[ks], bk[2], bk[3]);
                mma16816(accN[0], qfr[ks], bu[0], bu[1]);
                mma16816(accN[1], qfr[ks], bu[2], bu[3]);
            }

            // --- gate this slice (c-frag m16n16 -> a-frag m16k16) ---
            uint32_t aFr[4];
            aFr[0] = gate2(accM[0][0], accM[0][1], accN[0][0], accN[0][1]);
            aFr[1] = gate2(accM[0][2], accM[0][3], accN[0][2], accN[0][3]);
            aFr[2] = gate2(accM[1][0], accM[1][1], accN[1][0], accN[1][1]);
            aFr[3] = gate2(accM[1][2], accM[1][3], accN[1][2], accN[1][3]);

            // --- GEMM3 k-slice: O += A(:, pt*16:+16) V(pt*16:+16, :) ---
            #pragma unroll
            for (int p = 0; p < 8; ++p) {        // 8 x n16 covers d=128
                uint32_t bv[4];
                int g  = lane >> 3;
                int kr = pt * 16 + ((g & 1) << 3) + (lane & 7);
                uint32_t byt = p * 32 + ((g >> 1) << 4);
                ldsm_x4_t(stg + OFF_V + kr * 256 + (byt ^ ((kr & 7) << 4)), bv);
                mma16816(accO[2 * p + 0], aFr, bv[0], bv[1]);
                mma16816(accO[2 * p + 1], aFr, bv[2], bv[3]);
            }
        }

        __syncthreads();                  // stage (c&1) fully consumed
        if (c + 2 < NCHUNK) load_chunk(c + 2, c & 1);
        CP_COMMIT();                      // uniform group accounting
    }

    // ================= write O (16 rows x 128 cols per warp) =================
    {
        const int g = lane >> 2, q = lane & 3;
        const int r0 = wid * 16 + g;
        #pragma unroll
        for (int nt = 0; nt < 16; ++nt) {
            int col = nt * 8 + q * 2;
            *reinterpret_cast<float2*>(oB + (size_t)r0 * D + col) =
                make_float2(accO[nt][0], accO[nt][1]);
            *reinterpret_cast<float2*>(oB + (size_t)(r0 + 8) * D + col) =
                make_float2(accO[nt][2], accO[nt][3]);
        }
    }
}

// ======================= launch =======================

extern "C" void kernel_launch(void* const* d_in, const int* in_sizes, int n_in,
                              void* d_out, int out_size) {
    const float* Q = (const float*)d_in[0];
    const float* K = (const float*)d_in[1];
    const float* U = (const float*)d_in[2];
    const float* V = (const float*)d_in[3];
    float* O = (float*)d_out;

    dim3 gk((HK * NI * D / 4) / 256, 3);
    conv_kuv<<<gk, 256>>>(K, U, V);

    cudaFuncSetAttribute(flash_mlp_mma,
                         cudaFuncAttributeMaxDynamicSharedMemorySize, SMEM_TOTAL);
    dim3 grid(S / BM, NB * NH);   // (32, 32)
    flash_mlp_mma<<<grid, THREADS, SMEM_TOTAL>>>(Q, O);
}